// round 9
// baseline (speedup 1.0000x reference)
#include <cuda_runtime.h>
#include <cstdint>
#include <math.h>

#define NT 256
#define TILE 32
#define G_OFF    12672        // seg1 size: 96*132 floats (v1 A-tile is largest)
#define SMEM_FLOATS 18944     // seg1 + G (32*196)  = 75776 bytes

// Pre-converted tf32 weights, permuted per-k8-chunk N-major (filled by prep_weights)
#define W1S_OFF   0
#define W2S_OFF   114688
#define W1V1_OFF  180224
#define W2V1_OFF  196608
#define W1V2_OFF  212992
#define W2V2_OFF  217088
#define WBUF_SZ   221184
__device__ float WBUF[WBUF_SZ];

static __device__ __forceinline__ float f2tff(float f){
  uint32_t u; asm("cvt.rna.tf32.f32 %0, %1;" : "=r"(u) : "f"(f));
  return __uint_as_float(u);
}

static __device__ __forceinline__ void mma8(float* d, uint32_t a0, uint32_t a1,
                                            uint32_t a2, uint32_t a3,
                                            uint32_t b0, uint32_t b1){
  asm volatile("mma.sync.aligned.m16n8k8.row.col.f32.tf32.tf32.f32 "
      "{%0,%1,%2,%3}, {%4,%5,%6,%7}, {%8,%9}, {%0,%1,%2,%3};"
      : "+f"(d[0]), "+f"(d[1]), "+f"(d[2]), "+f"(d[3])
      : "r"(a0), "r"(a1), "r"(a2), "r"(a3), "r"(b0), "r"(b1));
}

// One ldmatrix.x4 = whole 16x8 tf32 A fragment (a0..a3) for one m16 tile.
static __device__ __forceinline__ void ldsm4(uint32_t* r, uint32_t addr){
  asm volatile("ldmatrix.sync.aligned.m8n8.x4.shared.b16 {%0,%1,%2,%3}, [%4];"
      : "=r"(r[0]), "=r"(r[1]), "=r"(r[2]), "=r"(r[3]) : "r"(addr));
}

// Register-free pipeline deepening: pull the line into L1 ahead of the LDG.
static __device__ __forceinline__ void pf_l1(const void* p){
  asm volatile("prefetch.global.L1 [%0];" :: "l"(p));
}

// ---------------------------------------------------------------------------
// Init kernel: tf32-convert + permute weights into k8-chunked N-major layout:
//   WBUF[off + kc*N*8 + n*8 + w] = tf32( W[(kc*8 + (w&1)*4 + (w>>1)) * N + n] )
// ---------------------------------------------------------------------------
__global__ void prep_weights(const float* __restrict__ w1s,
                             const float* __restrict__ w1v1,
                             const float* __restrict__ w1v2,
                             const float* __restrict__ w2s,
                             const float* __restrict__ w2v1,
                             const float* __restrict__ w2v2)
{
  int idx = blockIdx.x * blockDim.x + threadIdx.x;
  if (idx >= WBUF_SZ) return;
  const float* src; int N, loc;
  if      (idx < W2S_OFF)  { src = w1s;  N = 448; loc = idx - W1S_OFF;  }
  else if (idx < W1V1_OFF) { src = w2s;  N = 256; loc = idx - W2S_OFF;  }
  else if (idx < W2V1_OFF) { src = w1v1; N = 128; loc = idx - W1V1_OFF; }
  else if (idx < W1V2_OFF) { src = w2v1; N = 128; loc = idx - W2V1_OFF; }
  else if (idx < W2V2_OFF) { src = w1v2; N = 64;  loc = idx - W1V2_OFF; }
  else                     { src = w2v2; N = 64;  loc = idx - W2V2_OFF; }
  int kc = loc / (N*8); int r = loc - kc*N*8; int n = r >> 3; int w = r & 7;
  int k = kc*8 + (w&1)*4 + (w>>1);
  WBUF[idx] = f2tff(src[k*N + n]);
}

// ---------------------------------------------------------------------------
// acc += A(SMEM tf32, pitch PA, ldmatrix.x4, distance-1 pipe)
//      @ B(WBUF k8-packed, LDG.64 distance-1 + prefetch.L1 distance-3).
// Proven R8 shape; prefetch is the only addition. No barriers inside.
// ---------------------------------------------------------------------------
template<int K, int N, int WM, int WN, int PA>
static __device__ __forceinline__ void run_gemm(const float* __restrict__ gB,
                  uint32_t As_u32, float* acc, int lane, int mi, int nj)
{
  constexpr int NK8 = K/8;
  constexpr int PD  = 3;          // prefetch distance in k8 steps
  const float2* __restrict__ bp = reinterpret_cast<const float2*>(gB)
      + (lane & 3) + ((nj*WN)*8 + (lane>>2))*4;
  const int g = lane >> 3, r = lane & 7;
  const uint32_t aaddr = As_u32
      + ((uint32_t)(((mi*WM)*16 + r + (g&1)*8)*PA + (g>>1)*4))*4u;

  float2   b[2][WN];
  uint32_t a[2][WM][4];
  #pragma unroll
  for (int wn=0; wn<WN; wn++) b[0][wn] = __ldg(bp + wn*32);
  // prefetch steps 1..PD-1 so the distance-1 loads below start hitting L1
  #pragma unroll
  for (int pk=1; pk<PD && pk<NK8; pk++){
    #pragma unroll
    for (int wn=0; wn<WN; wn++) pf_l1(bp + pk*(N*4) + wn*32);
  }
  #pragma unroll
  for (int wm=0; wm<WM; wm++) ldsm4(a[0][wm], aaddr + wm*(16*PA*4));

  #pragma unroll 4
  for (int kc=0; kc<NK8; kc++){
    const int cur = kc & 1, nxt = cur ^ 1;
    if (kc+PD < NK8){
      #pragma unroll
      for (int wn=0; wn<WN; wn++) pf_l1(bp + (kc+PD)*(N*4) + wn*32);
    }
    if (kc+1 < NK8){
      #pragma unroll
      for (int wn=0; wn<WN; wn++) b[nxt][wn] = __ldg(bp + (kc+1)*(N*4) + wn*32);
      #pragma unroll
      for (int wm=0; wm<WM; wm++) ldsm4(a[nxt][wm], aaddr + wm*(16*PA*4) + (kc+1)*32);
    }
    #pragma unroll
    for (int wn=0; wn<WN; wn++){
      uint32_t b0 = __float_as_uint(b[cur][wn].x);
      uint32_t b1 = __float_as_uint(b[cur][wn].y);
      #pragma unroll
      for (int wm=0; wm<WM; wm++)
        mma8(acc+(wm*WN+wn)*4, a[cur][wm][0],a[cur][wm][1],
             a[cur][wm][2],a[cur][wm][3], b0, b1);
    }
  }
}

static __device__ __forceinline__ float sspf(float v, float cssp){
  float sp = fmaxf(v, 0.0f) + log1pf(expf(-fabsf(v)));
  return cssp * (sp - 0.69314718055994531f);
}

__global__ void __launch_bounds__(NT, 2)
resblk_kernel(const float* __restrict__ x, float* __restrict__ out, float cssp)
{
  extern __shared__ float sm[];
  float* seg1 = sm;
  float* G    = sm + G_OFF;
  uint32_t sm_u32;
  { uint32_t a; asm("{ .reg .u64 t; cvta.to.shared.u64 t, %1; cvt.u32.u64 %0, t; }"
                    : "=r"(a) : "l"(sm)); sm_u32 = a; }

  const int tid  = threadIdx.x;
  const int lane = tid & 31;
  const int warp = tid >> 5;            // 0..7
  const int nj2  = warp;                // scalar path: 1M x 8N
  const int mi4  = warp >> 2;           // vector paths: 2M x 4N
  const int nj4  = warp & 3;
  const int n0   = blockIdx.x * TILE;
  const float RS128 = 0.08838834764831845f;
  const float RS64  = 0.125f;

  // ================= scalar path =================
  // A0 = tf32(x0 tile)  [32 x 256], pitch 260
  for (int t=tid; t<(TILE*256)/4; t+=NT){
    int e=t*4; int ln=e>>8; int col=e&255;
    float4 v = *reinterpret_cast<const float4*>(x + (size_t)(n0+ln)*960 + col);
    *reinterpret_cast<float4*>(seg1 + ln*260 + col) =
      make_float4(f2tff(v.x),f2tff(v.y),f2tff(v.z),f2tff(v.w));
  }
  __syncthreads();
  // s = A0 @ w1s / 16, SSP -> scalars(seg1, tf32) + gates(G, fp32)
  {
    float acc[56];
    #pragma unroll
    for (int i=0;i<56;i++) acc[i]=0.f;
    run_gemm<256,448,2,7,260>(&WBUF[W1S_OFF], sm_u32, acc, lane, 0, nj2);
    __syncthreads();
    #pragma unroll
    for (int wm=0; wm<2; wm++){
      #pragma unroll
      for (int wn=0; wn<7; wn++){
        #pragma unroll
        for (int q=0;q<4;q++){
          int row = wm*16 + (lane>>2) + ((q&2)<<2);
          int col = (nj2*7+wn)*8 + ((lane&3)<<1) + (q&1);
          float h = sspf(acc[(wm*7+wn)*4+q]*0.0625f, cssp);
          if (col < 256) seg1[row*260 + col] = f2tff(h);
          else           G[row*196 + (col-256)] = h;
        }
      }
    }
  }
  __syncthreads();
  // y0 = scalars @ w2s / 16 ; stage then coalesced residual write
  {
    float acc[32];
    #pragma unroll
    for (int i=0;i<32;i++) acc[i]=0.f;
    run_gemm<256,256,2,4,260>(&WBUF[W2S_OFF], sm_u32, acc, lane, 0, nj2);
    __syncthreads();
    #pragma unroll
    for (int wm=0; wm<2; wm++){
      #pragma unroll
      for (int wn=0; wn<4; wn++){
        #pragma unroll
        for (int q=0;q<4;q++){
          int row = wm*16 + (lane>>2) + ((q&2)<<2);
          int col = (nj2*4+wn)*8 + ((lane&3)<<1) + (q&1);
          seg1[row*260 + col] = acc[(wm*4+wn)*4+q]*0.0625f;
        }
      }
    }
    __syncthreads();
    for (int t=tid; t<TILE*64; t+=NT){
      int ln=t>>6; int j=(t&63)*4;
      size_t off = (size_t)(n0+ln)*960 + j;
      float4 xr = *reinterpret_cast<const float4*>(x + off);
      float4 yv = *reinterpret_cast<const float4*>(seg1 + ln*260 + j);
      *reinterpret_cast<float4*>(out + off) =
        make_float4(xr.x+yv.x, xr.y+yv.y, xr.z+yv.z, xr.w+yv.w);
    }
  }
  __syncthreads();

  // ================= v1 path =================
  // A1[c*32+n][i] = tf32(x[n, 256+3i+c])  [96 x 128], pitch 132
  for (int t=tid; t<(TILE*384)/4; t+=NT){
    int e=t*4; int ln=e/384; int j=e-ln*384;
    float4 v = *reinterpret_cast<const float4*>(x + (size_t)(n0+ln)*960 + 256 + j);
    float vv[4]={v.x,v.y,v.z,v.w};
    #pragma unroll
    for (int q=0;q<4;q++){
      int jj=j+q; int i3=jj/3; int c=jj-i3*3;
      seg1[(c*32+ln)*132 + i3] = f2tff(vv[q]);
    }
  }
  __syncthreads();
  // V1 = A1 @ w1v1 * rs128, gated, in place (tf32)
  {
    float acc[48];
    #pragma unroll
    for (int i=0;i<48;i++) acc[i]=0.f;
    run_gemm<128,128,3,4,132>(&WBUF[W1V1_OFF], sm_u32, acc, lane, mi4, nj4);
    __syncthreads();
    #pragma unroll
    for (int wm=0; wm<3; wm++){
      #pragma unroll
      for (int wn=0; wn<4; wn++){
        #pragma unroll
        for (int q=0;q<4;q++){
          int row = (mi4*3+wm)*16 + (lane>>2) + ((q&2)<<2);
          int col = (nj4*4+wn)*8 + ((lane&3)<<1) + (q&1);
          float g = G[(row&31)*196 + col];
          seg1[row*132 + col] = f2tff(acc[(wm*4+wn)*4+q]*RS128*g);
        }
      }
    }
  }
  __syncthreads();
  // Y1 = V1 @ w2v1 * rs128 -> stage [n][3o+c] -> coalesced residual write
  {
    float acc[48];
    #pragma unroll
    for (int i=0;i<48;i++) acc[i]=0.f;
    run_gemm<128,128,3,4,132>(&WBUF[W2V1_OFF], sm_u32, acc, lane, mi4, nj4);
    __syncthreads();
    #pragma unroll
    for (int wm=0; wm<3; wm++){
      #pragma unroll
      for (int wn=0; wn<4; wn++){
        #pragma unroll
        for (int q=0;q<4;q++){
          int row = (mi4*3+wm)*16 + (lane>>2) + ((q&2)<<2);
          int col = (nj4*4+wn)*8 + ((lane&3)<<1) + (q&1);
          int n = row & 31; int c = row >> 5;
          seg1[n*388 + 3*col + c] = acc[(wm*4+wn)*4+q]*RS128;
        }
      }
    }
    __syncthreads();
    for (int t=tid; t<TILE*96; t+=NT){
      int ln=t/96; int j=(t-ln*96)*4;
      size_t off = (size_t)(n0+ln)*960 + 256 + j;
      float4 xr = *reinterpret_cast<const float4*>(x + off);
      float4 yv = *reinterpret_cast<const float4*>(seg1 + ln*388 + j);
      *reinterpret_cast<float4*>(out + off) =
        make_float4(xr.x+yv.x, xr.y+yv.y, xr.z+yv.z, xr.w+yv.w);
    }
  }
  __syncthreads();

  // ================= v2 path =================
  // A2[c*32+n][i] = tf32(x[n, 640+5i+c])  [160 x 64], pitch 68
  for (int t=tid; t<(TILE*320)/4; t+=NT){
    int e=t*4; int ln=e/320; int j=e-ln*320;
    float4 v = *reinterpret_cast<const float4*>(x + (size_t)(n0+ln)*960 + 640 + j);
    float vv[4]={v.x,v.y,v.z,v.w};
    #pragma unroll
    for (int q=0;q<4;q++){
      int jj=j+q; int i5=jj/5; int c=jj-i5*5;
      seg1[(c*32+ln)*68 + i5] = f2tff(vv[q]);
    }
  }
  __syncthreads();
  // V2 = A2 @ w1v2 * rs64, gated, in place (tf32)
  {
    float acc[40];
    #pragma unroll
    for (int i=0;i<40;i++) acc[i]=0.f;
    run_gemm<64,64,5,2,68>(&WBUF[W1V2_OFF], sm_u32, acc, lane, mi4, nj4);
    __syncthreads();
    #pragma unroll
    for (int wm=0; wm<5; wm++){
      #pragma unroll
      for (int wn=0; wn<2; wn++){
        #pragma unroll
        for (int q=0;q<4;q++){
          int row = (mi4*5+wm)*16 + (lane>>2) + ((q&2)<<2);
          int col = (nj4*2+wn)*8 + ((lane&3)<<1) + (q&1);
          float g = G[(row&31)*196 + 128 + col];
          seg1[row*68 + col] = f2tff(acc[(wm*2+wn)*4+q]*RS64*g);
        }
      }
    }
  }
  __syncthreads();
  // Y2 = V2 @ w2v2 * rs64 -> stage [n][5o+c] -> coalesced residual write
  {
    float acc[40];
    #pragma unroll
    for (int i=0;i<40;i++) acc[i]=0.f;
    run_gemm<64,64,5,2,68>(&WBUF[W2V2_OFF], sm_u32, acc, lane, mi4, nj4);
    __syncthreads();
    #pragma unroll
    for (int wm=0; wm<5; wm++){
      #pragma unroll
      for (int wn=0; wn<2; wn++){
        #pragma unroll
        for (int q=0;q<4;q++){
          int row = (mi4*5+wm)*16 + (lane>>2) + ((q&2)<<2);
          int col = (nj4*2+wn)*8 + ((lane&3)<<1) + (q&1);
          int n = row & 31; int c = row >> 5;
          seg1[n*324 + 5*col + c] = acc[(wm*2+wn)*4+q]*RS64;
        }
      }
    }
    __syncthreads();
    for (int t=tid; t<TILE*80; t+=NT){
      int ln=t/80; int j=(t-ln*80)*4;
      size_t off = (size_t)(n0+ln)*960 + 640 + j;
      float4 xr = *reinterpret_cast<const float4*>(x + off);
      float4 yv = *reinterpret_cast<const float4*>(seg1 + ln*324 + j);
      *reinterpret_cast<float4*>(out + off) =
        make_float4(xr.x+yv.x, xr.y+yv.y, xr.z+yv.z, xr.w+yv.w);
    }
  }
}

static double compute_cssp_host(){
  const int NP = 200001;
  const double LOG2 = 0.6931471805599453094172321214581766;
  double s = 0.0;
  for (int i=0;i<NP;i++){
    double z = -10.0 + (20.0 * i) / (NP - 1);
    double phi = exp(-0.5*z*z) / sqrt(2.0*3.14159265358979323846);
    double sp  = (z > 0.0) ? (z + log1p(exp(-z))) : log1p(exp(z));
    double f   = sp - LOG2;
    double w   = (i==0 || i==NP-1) ? 0.5 : 1.0;
    s += w * f * f * phi;
  }
  s *= 20.0 / (NP - 1);
  return 1.0 / sqrt(s);
}

extern "C" void kernel_launch(void* const* d_in, const int* in_sizes, int n_in,
                              void* d_out, int out_size) {
  const float* x    = (const float*)d_in[0];
  const float* w1s  = (const float*)d_in[1];
  const float* w1v1 = (const float*)d_in[2];
  const float* w1v2 = (const float*)d_in[3];
  const float* w2s  = (const float*)d_in[4];
  const float* w2v1 = (const float*)d_in[5];
  const float* w2v2 = (const float*)d_in[6];
  float* out = (float*)d_out;

  int n = in_sizes[0] / 960;

  static bool attr_done = false;
  if (!attr_done){
    cudaFuncSetAttribute(resblk_kernel,
        cudaFuncAttributeMaxDynamicSharedMemorySize, SMEM_FLOATS*4);
    attr_done = true;
  }
  static const float cssp = (float)compute_cssp_host();

  prep_weights<<<(WBUF_SZ + NT - 1)/NT, NT>>>(w1s, w1v1, w1v2, w2s, w2v1, w2v2);
  resblk_kernel<<<n/TILE, NT, SMEM_FLOATS*4>>>(x, out, cssp);
}

// round 10
// speedup vs baseline: 1.1256x; 1.1256x over previous
#include <cuda_runtime.h>
#include <cstdint>
#include <math.h>

#define NT 256
#define TILE 32
#define G_OFF    12672        // seg1 size: 96*132 floats (v1 A-tile is largest)
#define SMEM_FLOATS 18944     // seg1 + G (32*196)  = 75776 bytes

// Pre-converted tf32 weights (filled by prep_weights).
// w1s: k8-chunk N-major packing (float2 per lane). Others: k16-chunk packing
// (float4 per lane = B fragments for two consecutive k8 steps).
#define W1S_OFF   0
#define W2S_OFF   114688
#define W1V1_OFF  180224
#define W2V1_OFF  196608
#define W1V2_OFF  212992
#define W2V2_OFF  217088
#define WBUF_SZ   221184
__device__ float WBUF[WBUF_SZ];

static __device__ __forceinline__ float f2tff(float f){
  uint32_t u; asm("cvt.rna.tf32.f32 %0, %1;" : "=r"(u) : "f"(f));
  return __uint_as_float(u);
}

static __device__ __forceinline__ void mma8(float* d, uint32_t a0, uint32_t a1,
                                            uint32_t a2, uint32_t a3,
                                            uint32_t b0, uint32_t b1){
  asm volatile("mma.sync.aligned.m16n8k8.row.col.f32.tf32.tf32.f32 "
      "{%0,%1,%2,%3}, {%4,%5,%6,%7}, {%8,%9}, {%0,%1,%2,%3};"
      : "+f"(d[0]), "+f"(d[1]), "+f"(d[2]), "+f"(d[3])
      : "r"(a0), "r"(a1), "r"(a2), "r"(a3), "r"(b0), "r"(b1));
}

// One ldmatrix.x4 = whole 16x8 tf32 A fragment (a0..a3) for one m16 tile.
static __device__ __forceinline__ void ldsm4(uint32_t* r, uint32_t addr){
  asm volatile("ldmatrix.sync.aligned.m8n8.x4.shared.b16 {%0,%1,%2,%3}, [%4];"
      : "=r"(r[0]), "=r"(r[1]), "=r"(r[2]), "=r"(r[3]) : "r"(addr));
}

// ---------------------------------------------------------------------------
// Init kernel.
// w1s (8-pack):  WBUF[kc*N*8  + n*8  + w] = tf32(W[(kc*8  + (w&1)*4 + (w>>1))*N + n])
// others (16-):  WBUF[kc*N*16 + n*16 + w] = tf32(W[(kc*16 + (w&3)*4 + (w>>2))*N + n])
//   -> LDG.128 at [n*16 + p*4] yields k = {p, p+4, p+8, p+12}: fragments for
//      both k8 sub-steps of the k16 chunk, lane p.
// ---------------------------------------------------------------------------
__global__ void prep_weights(const float* __restrict__ w1s,
                             const float* __restrict__ w1v1,
                             const float* __restrict__ w1v2,
                             const float* __restrict__ w2s,
                             const float* __restrict__ w2v1,
                             const float* __restrict__ w2v2)
{
  int idx = blockIdx.x * blockDim.x + threadIdx.x;
  if (idx >= WBUF_SZ) return;
  const float* src; int N, loc; bool p16 = true;
  if      (idx < W2S_OFF)  { src = w1s;  N = 448; loc = idx - W1S_OFF; p16 = false; }
  else if (idx < W1V1_OFF) { src = w2s;  N = 256; loc = idx - W2S_OFF;  }
  else if (idx < W2V1_OFF) { src = w1v1; N = 128; loc = idx - W1V1_OFF; }
  else if (idx < W1V2_OFF) { src = w2v1; N = 128; loc = idx - W2V1_OFF; }
  else if (idx < W2V2_OFF) { src = w1v2; N = 64;  loc = idx - W1V2_OFF; }
  else                     { src = w2v2; N = 64;  loc = idx - W2V2_OFF; }
  int k;
  int n;
  if (p16){
    int kc = loc / (N*16); int r = loc - kc*N*16; n = r >> 4; int w = r & 15;
    k = kc*16 + (w&3)*4 + (w>>2);
  } else {
    int kc = loc / (N*8);  int r = loc - kc*N*8;  n = r >> 3; int w = r & 7;
    k = kc*8 + (w&1)*4 + (w>>1);
  }
  WBUF[idx] = f2tff(src[k*N + n]);
}

// ---------------------------------------------------------------------------
// GEMM1 path (k8 float2 B, proven R8 shape — unchanged).
// ---------------------------------------------------------------------------
template<int K, int N, int WM, int WN, int PA>
static __device__ __forceinline__ void run_gemm8(const float* __restrict__ gB,
                  uint32_t As_u32, float* acc, int lane, int mi, int nj)
{
  constexpr int NK8 = K/8;
  const float2* __restrict__ bp = reinterpret_cast<const float2*>(gB)
      + (lane & 3) + ((nj*WN)*8 + (lane>>2))*4;
  const int g = lane >> 3, r = lane & 7;
  const uint32_t aaddr = As_u32
      + ((uint32_t)(((mi*WM)*16 + r + (g&1)*8)*PA + (g>>1)*4))*4u;

  float2   b[2][WN];
  uint32_t a[2][WM][4];
  #pragma unroll
  for (int wn=0; wn<WN; wn++) b[0][wn] = __ldg(bp + wn*32);
  #pragma unroll
  for (int wm=0; wm<WM; wm++) ldsm4(a[0][wm], aaddr + wm*(16*PA*4));

  #pragma unroll 4
  for (int kc=0; kc<NK8; kc++){
    const int cur = kc & 1, nxt = cur ^ 1;
    if (kc+1 < NK8){
      #pragma unroll
      for (int wn=0; wn<WN; wn++) b[nxt][wn] = __ldg(bp + (kc+1)*(N*4) + wn*32);
      #pragma unroll
      for (int wm=0; wm<WM; wm++) ldsm4(a[nxt][wm], aaddr + wm*(16*PA*4) + (kc+1)*32);
    }
    #pragma unroll
    for (int wn=0; wn<WN; wn++){
      uint32_t b0 = __float_as_uint(b[cur][wn].x);
      uint32_t b1 = __float_as_uint(b[cur][wn].y);
      #pragma unroll
      for (int wm=0; wm<WM; wm++)
        mma8(acc+(wm*WN+wn)*4, a[cur][wm][0],a[cur][wm][1],
             a[cur][wm][2],a[cur][wm][3], b0, b1);
    }
  }
}

// ---------------------------------------------------------------------------
// k16 path: one LDG.128 per (wn, k16 chunk) = B for two k8 sub-steps.
// A via ldmatrix, parity-indexed (a[0]=even k8, a[1]=odd k8), distance-1.
// k accumulation order identical to run_gemm8 (strictly sequential).
// ---------------------------------------------------------------------------
template<int K, int N, int WM, int WN, int PA>
static __device__ __forceinline__ void run_gemm16(const float* __restrict__ gB,
                  uint32_t As_u32, float* acc, int lane, int mi, int nj)
{
  constexpr int NK16 = K/16;
  const float4* __restrict__ bp = reinterpret_cast<const float4*>(gB)
      + (lane & 3) + ((nj*WN)*8 + (lane>>2))*4;
  const int g = lane >> 3, r = lane & 7;
  const uint32_t aaddr = As_u32
      + ((uint32_t)(((mi*WM)*16 + r + (g&1)*8)*PA + (g>>1)*4))*4u;

  float4   b[2][WN];
  uint32_t a[2][WM][4];
  #pragma unroll
  for (int wn=0; wn<WN; wn++) b[0][wn] = __ldg(bp + wn*32);
  #pragma unroll
  for (int wm=0; wm<WM; wm++) ldsm4(a[0][wm], aaddr + wm*(16*PA*4));   // k8 = 0

  #pragma unroll
  for (int kc=0; kc<NK16; kc++){
    const int cur = kc & 1, nxt = cur ^ 1;
    if (kc+1 < NK16){
      #pragma unroll
      for (int wn=0; wn<WN; wn++) b[nxt][wn] = __ldg(bp + (kc+1)*(N*4) + wn*32);
    }
    // A for odd sub-step (k8 = 2kc+1)
    #pragma unroll
    for (int wm=0; wm<WM; wm++)
      ldsm4(a[1][wm], aaddr + wm*(16*PA*4) + (2*kc+1)*32);
    // sub-step 0: k8 = 2kc, uses a[0], b .x/.y
    #pragma unroll
    for (int wn=0; wn<WN; wn++){
      uint32_t b0 = __float_as_uint(b[cur][wn].x);
      uint32_t b1 = __float_as_uint(b[cur][wn].y);
      #pragma unroll
      for (int wm=0; wm<WM; wm++)
        mma8(acc+(wm*WN+wn)*4, a[0][wm][0],a[0][wm][1],a[0][wm][2],a[0][wm][3], b0, b1);
    }
    // A for next even sub-step (k8 = 2kc+2)
    if (kc+1 < NK16){
      #pragma unroll
      for (int wm=0; wm<WM; wm++)
        ldsm4(a[0][wm], aaddr + wm*(16*PA*4) + (2*kc+2)*32);
    }
    // sub-step 1: k8 = 2kc+1, uses a[1], b .z/.w
    #pragma unroll
    for (int wn=0; wn<WN; wn++){
      uint32_t b2 = __float_as_uint(b[cur][wn].z);
      uint32_t b3 = __float_as_uint(b[cur][wn].w);
      #pragma unroll
      for (int wm=0; wm<WM; wm++)
        mma8(acc+(wm*WN+wn)*4, a[1][wm][0],a[1][wm][1],a[1][wm][2],a[1][wm][3], b2, b3);
    }
  }
}

static __device__ __forceinline__ float sspf(float v, float cssp){
  float sp = fmaxf(v, 0.0f) + log1pf(expf(-fabsf(v)));
  return cssp * (sp - 0.69314718055994531f);
}

__global__ void __launch_bounds__(NT, 2)
resblk_kernel(const float* __restrict__ x, float* __restrict__ out, float cssp)
{
  extern __shared__ float sm[];
  float* seg1 = sm;
  float* G    = sm + G_OFF;
  uint32_t sm_u32;
  { uint32_t a; asm("{ .reg .u64 t; cvta.to.shared.u64 t, %1; cvt.u32.u64 %0, t; }"
                    : "=r"(a) : "l"(sm)); sm_u32 = a; }

  const int tid  = threadIdx.x;
  const int lane = tid & 31;
  const int warp = tid >> 5;            // 0..7
  const int nj2  = warp;                // scalar path: 1M x 8N
  const int mi4  = warp >> 2;           // vector paths: 2M x 4N
  const int nj4  = warp & 3;
  const int n0   = blockIdx.x * TILE;
  const float RS128 = 0.08838834764831845f;
  const float RS64  = 0.125f;

  // ================= scalar path =================
  // A0 = tf32(x0 tile)  [32 x 256], pitch 260
  for (int t=tid; t<(TILE*256)/4; t+=NT){
    int e=t*4; int ln=e>>8; int col=e&255;
    float4 v = *reinterpret_cast<const float4*>(x + (size_t)(n0+ln)*960 + col);
    *reinterpret_cast<float4*>(seg1 + ln*260 + col) =
      make_float4(f2tff(v.x),f2tff(v.y),f2tff(v.z),f2tff(v.w));
  }
  __syncthreads();
  // s = A0 @ w1s / 16, SSP -> scalars(seg1, tf32) + gates(G, fp32)
  {
    float acc[56];
    #pragma unroll
    for (int i=0;i<56;i++) acc[i]=0.f;
    run_gemm8<256,448,2,7,260>(&WBUF[W1S_OFF], sm_u32, acc, lane, 0, nj2);
    __syncthreads();
    #pragma unroll
    for (int wm=0; wm<2; wm++){
      #pragma unroll
      for (int wn=0; wn<7; wn++){
        #pragma unroll
        for (int q=0;q<4;q++){
          int row = wm*16 + (lane>>2) + ((q&2)<<2);
          int col = (nj2*7+wn)*8 + ((lane&3)<<1) + (q&1);
          float h = sspf(acc[(wm*7+wn)*4+q]*0.0625f, cssp);
          if (col < 256) seg1[row*260 + col] = f2tff(h);
          else           G[row*196 + (col-256)] = h;
        }
      }
    }
  }
  __syncthreads();
  // y0 = scalars @ w2s / 16 ; stage then coalesced residual write
  {
    float acc[32];
    #pragma unroll
    for (int i=0;i<32;i++) acc[i]=0.f;
    run_gemm16<256,256,2,4,260>(&WBUF[W2S_OFF], sm_u32, acc, lane, 0, nj2);
    __syncthreads();
    #pragma unroll
    for (int wm=0; wm<2; wm++){
      #pragma unroll
      for (int wn=0; wn<4; wn++){
        #pragma unroll
        for (int q=0;q<4;q++){
          int row = wm*16 + (lane>>2) + ((q&2)<<2);
          int col = (nj2*4+wn)*8 + ((lane&3)<<1) + (q&1);
          seg1[row*260 + col] = acc[(wm*4+wn)*4+q]*0.0625f;
        }
      }
    }
    __syncthreads();
    for (int t=tid; t<TILE*64; t+=NT){
      int ln=t>>6; int j=(t&63)*4;
      size_t off = (size_t)(n0+ln)*960 + j;
      float4 xr = *reinterpret_cast<const float4*>(x + off);
      float4 yv = *reinterpret_cast<const float4*>(seg1 + ln*260 + j);
      *reinterpret_cast<float4*>(out + off) =
        make_float4(xr.x+yv.x, xr.y+yv.y, xr.z+yv.z, xr.w+yv.w);
    }
  }
  __syncthreads();

  // ================= v1 path =================
  // A1[c*32+n][i] = tf32(x[n, 256+3i+c])  [96 x 128], pitch 132
  for (int t=tid; t<(TILE*384)/4; t+=NT){
    int e=t*4; int ln=e/384; int j=e-ln*384;
    float4 v = *reinterpret_cast<const float4*>(x + (size_t)(n0+ln)*960 + 256 + j);
    float vv[4]={v.x,v.y,v.z,v.w};
    #pragma unroll
    for (int q=0;q<4;q++){
      int jj=j+q; int i3=jj/3; int c=jj-i3*3;
      seg1[(c*32+ln)*132 + i3] = f2tff(vv[q]);
    }
  }
  __syncthreads();
  // V1 = A1 @ w1v1 * rs128, gated, in place (tf32)
  {
    float acc[48];
    #pragma unroll
    for (int i=0;i<48;i++) acc[i]=0.f;
    run_gemm16<128,128,3,4,132>(&WBUF[W1V1_OFF], sm_u32, acc, lane, mi4, nj4);
    __syncthreads();
    #pragma unroll
    for (int wm=0; wm<3; wm++){
      #pragma unroll
      for (int wn=0; wn<4; wn++){
        #pragma unroll
        for (int q=0;q<4;q++){
          int row = (mi4*3+wm)*16 + (lane>>2) + ((q&2)<<2);
          int col = (nj4*4+wn)*8 + ((lane&3)<<1) + (q&1);
          float g = G[(row&31)*196 + col];
          seg1[row*132 + col] = f2tff(acc[(wm*4+wn)*4+q]*RS128*g);
        }
      }
    }
  }
  __syncthreads();
  // Y1 = V1 @ w2v1 * rs128 -> stage [n][3o+c] -> coalesced residual write
  {
    float acc[48];
    #pragma unroll
    for (int i=0;i<48;i++) acc[i]=0.f;
    run_gemm16<128,128,3,4,132>(&WBUF[W2V1_OFF], sm_u32, acc, lane, mi4, nj4);
    __syncthreads();
    #pragma unroll
    for (int wm=0; wm<3; wm++){
      #pragma unroll
      for (int wn=0; wn<4; wn++){
        #pragma unroll
        for (int q=0;q<4;q++){
          int row = (mi4*3+wm)*16 + (lane>>2) + ((q&2)<<2);
          int col = (nj4*4+wn)*8 + ((lane&3)<<1) + (q&1);
          int n = row & 31; int c = row >> 5;
          seg1[n*388 + 3*col + c] = acc[(wm*4+wn)*4+q]*RS128;
        }
      }
    }
    __syncthreads();
    for (int t=tid; t<TILE*96; t+=NT){
      int ln=t/96; int j=(t-ln*96)*4;
      size_t off = (size_t)(n0+ln)*960 + 256 + j;
      float4 xr = *reinterpret_cast<const float4*>(x + off);
      float4 yv = *reinterpret_cast<const float4*>(seg1 + ln*388 + j);
      *reinterpret_cast<float4*>(out + off) =
        make_float4(xr.x+yv.x, xr.y+yv.y, xr.z+yv.z, xr.w+yv.w);
    }
  }
  __syncthreads();

  // ================= v2 path =================
  // A2[c*32+n][i] = tf32(x[n, 640+5i+c])  [160 x 64], pitch 68
  for (int t=tid; t<(TILE*320)/4; t+=NT){
    int e=t*4; int ln=e/320; int j=e-ln*320;
    float4 v = *reinterpret_cast<const float4*>(x + (size_t)(n0+ln)*960 + 640 + j);
    float vv[4]={v.x,v.y,v.z,v.w};
    #pragma unroll
    for (int q=0;q<4;q++){
      int jj=j+q; int i5=jj/5; int c=jj-i5*5;
      seg1[(c*32+ln)*68 + i5] = f2tff(vv[q]);
    }
  }
  __syncthreads();
  // V2 = A2 @ w1v2 * rs64, gated, in place (tf32)
  {
    float acc[40];
    #pragma unroll
    for (int i=0;i<40;i++) acc[i]=0.f;
    run_gemm16<64,64,5,2,68>(&WBUF[W1V2_OFF], sm_u32, acc, lane, mi4, nj4);
    __syncthreads();
    #pragma unroll
    for (int wm=0; wm<5; wm++){
      #pragma unroll
      for (int wn=0; wn<2; wn++){
        #pragma unroll
        for (int q=0;q<4;q++){
          int row = (mi4*5+wm)*16 + (lane>>2) + ((q&2)<<2);
          int col = (nj4*2+wn)*8 + ((lane&3)<<1) + (q&1);
          float g = G[(row&31)*196 + 128 + col];
          seg1[row*68 + col] = f2tff(acc[(wm*2+wn)*4+q]*RS64*g);
        }
      }
    }
  }
  __syncthreads();
  // Y2 = V2 @ w2v2 * rs64 -> stage [n][5o+c] -> coalesced residual write
  {
    float acc[40];
    #pragma unroll
    for (int i=0;i<40;i++) acc[i]=0.f;
    run_gemm16<64,64,5,2,68>(&WBUF[W2V2_OFF], sm_u32, acc, lane, mi4, nj4);
    __syncthreads();
    #pragma unroll
    for (int wm=0; wm<5; wm++){
      #pragma unroll
      for (int wn=0; wn<2; wn++){
        #pragma unroll
        for (int q=0;q<4;q++){
          int row = (mi4*5+wm)*16 + (lane>>2) + ((q&2)<<2);
          int col = (nj4*2+wn)*8 + ((lane&3)<<1) + (q&1);
          int n = row & 31; int c = row >> 5;
          seg1[n*324 + 5*col + c] = acc[(wm*2+wn)*4+q]*RS64;
        }
      }
    }
    __syncthreads();
    for (int t=tid; t<TILE*80; t+=NT){
      int ln=t/80; int j=(t-ln*80)*4;
      size_t off = (size_t)(n0+ln)*960 + 640 + j;
      float4 xr = *reinterpret_cast<const float4*>(x + off);
      float4 yv = *reinterpret_cast<const float4*>(seg1 + ln*324 + j);
      *reinterpret_cast<float4*>(out + off) =
        make_float4(xr.x+yv.x, xr.y+yv.y, xr.z+yv.z, xr.w+yv.w);
    }
  }
}

static double compute_cssp_host(){
  const int NP = 200001;
  const double LOG2 = 0.6931471805599453094172321214581766;
  double s = 0.0;
  for (int i=0;i<NP;i++){
    double z = -10.0 + (20.0 * i) / (NP - 1);
    double phi = exp(-0.5*z*z) / sqrt(2.0*3.14159265358979323846);
    double sp  = (z > 0.0) ? (z + log1p(exp(-z))) : log1p(exp(z));
    double f   = sp - LOG2;
    double w   = (i==0 || i==NP-1) ? 0.5 : 1.0;
    s += w * f * f * phi;
  }
  s *= 20.0 / (NP - 1);
  return 1.0 / sqrt(s);
}

extern "C" void kernel_launch(void* const* d_in, const int* in_sizes, int n_in,
                              void* d_out, int out_size) {
  const float* x    = (const float*)d_in[0];
  const float* w1s  = (const float*)d_in[1];
  const float* w1v1 = (const float*)d_in[2];
  const float* w1v2 = (const float*)d_in[3];
  const float* w2s  = (const float*)d_in[4];
  const float* w2v1 = (const float*)d_in[5];
  const float* w2v2 = (const float*)d_in[6];
  float* out = (float*)d_out;

  int n = in_sizes[0] / 960;

  static bool attr_done = false;
  if (!attr_done){
    cudaFuncSetAttribute(resblk_kernel,
        cudaFuncAttributeMaxDynamicSharedMemorySize, SMEM_FLOATS*4);
    attr_done = true;
  }
  static const float cssp = (float)compute_cssp_host();

  prep_weights<<<(WBUF_SZ + NT - 1)/NT, NT>>>(w1s, w1v1, w1v2, w2s, w2v1, w2v2);
  resblk_kernel<<<n/TILE, NT, SMEM_FLOATS*4>>>(x, out, cssp);
}

// round 11
// speedup vs baseline: 1.3537x; 1.2026x over previous
#include <cuda_runtime.h>
#include <cuda_fp16.h>
#include <cstdint>
#include <math.h>

#define NT 256
#define TILE 32
#define SEG_FLOATS 12416      // y1 stage (32 x 388 floats) is the largest occupant
#define G_OFF    12416
#define SMEM_FLOATS 18688     // + G (32 x 196 floats)  = 74752 bytes per CTA

// A-tile pitches in fp16 elements (row bytes = 16 * odd -> conflict-free ldmatrix)
#define PA0 264
#define PA1 136
#define PA2 72

// Pre-converted fp16 weights (filled by prep_weights).
// w1s: k16-chunk packing (uint2 per lane-fragment). Others: k32-chunk packing
// (uint4 per lane = B fragments for two consecutive m16n8k16 steps).
#define W1S_OFF   0
#define W2S_OFF   114688
#define W1V1_OFF  180224
#define W2V1_OFF  196608
#define W1V2_OFF  212992
#define W2V2_OFF  217088
#define WBUF_SZ   221184
__device__ __half WBUF[WBUF_SZ];

static __device__ __forceinline__ void mma16(float* d, const uint32_t* a,
                                             uint32_t b0, uint32_t b1){
  asm volatile("mma.sync.aligned.m16n8k16.row.col.f32.f16.f16.f32 "
      "{%0,%1,%2,%3}, {%4,%5,%6,%7}, {%8,%9}, {%0,%1,%2,%3};"
      : "+f"(d[0]), "+f"(d[1]), "+f"(d[2]), "+f"(d[3])
      : "r"(a[0]), "r"(a[1]), "r"(a[2]), "r"(a[3]), "r"(b0), "r"(b1));
}

// One ldmatrix.x4 = whole 16x16 fp16 A fragment (a0..a3) for one m16k16 tile.
static __device__ __forceinline__ void ldsm4(uint32_t* r, uint32_t addr){
  asm volatile("ldmatrix.sync.aligned.m8n8.x4.shared.b16 {%0,%1,%2,%3}, [%4];"
      : "=r"(r[0]), "=r"(r[1]), "=r"(r[2]), "=r"(r[3]) : "r"(addr));
}

// ---------------------------------------------------------------------------
// Init kernel: fp16-convert + permute weights.
// w1s (k16): WBUF[kc*N*16 + n*16 + w], w=q*4+j -> k = kc*16 + 2q + (j&1) + (j&2)*4
//   lane q's uint2 = fp16 {2q,2q+1 | 2q+8,2q+9} = B fragment of m16n8k16.
// others (k32): WBUF[kc*N*32 + n*32 + w], w=q*8+t -> k = kc*32 + (t>>2)*16 + 2q + (t&1) + (t&2)*4
//   lane q's uint4 = fragments for both k16 halves of the k32 chunk.
// ---------------------------------------------------------------------------
__global__ void prep_weights(const float* __restrict__ w1s,
                             const float* __restrict__ w1v1,
                             const float* __restrict__ w1v2,
                             const float* __restrict__ w2s,
                             const float* __restrict__ w2v1,
                             const float* __restrict__ w2v2)
{
  int idx = blockIdx.x * blockDim.x + threadIdx.x;
  if (idx >= WBUF_SZ) return;
  const float* src; int N, loc; bool p32 = true;
  if      (idx < W2S_OFF)  { src = w1s;  N = 448; loc = idx - W1S_OFF; p32 = false; }
  else if (idx < W1V1_OFF) { src = w2s;  N = 256; loc = idx - W2S_OFF;  }
  else if (idx < W2V1_OFF) { src = w1v1; N = 128; loc = idx - W1V1_OFF; }
  else if (idx < W1V2_OFF) { src = w2v1; N = 128; loc = idx - W2V1_OFF; }
  else if (idx < W2V2_OFF) { src = w1v2; N = 64;  loc = idx - W1V2_OFF; }
  else                     { src = w2v2; N = 64;  loc = idx - W2V2_OFF; }
  int k, n;
  if (p32){
    int kc = loc / (N*32); int r = loc - kc*N*32; n = r >> 5; int w = r & 31;
    int q = w >> 3, t = w & 7;
    k = kc*32 + (t>>2)*16 + 2*q + (t&1) + (t&2)*4;
  } else {
    int kc = loc / (N*16); int r = loc - kc*N*16; n = r >> 4; int w = r & 15;
    int q = w >> 2, j = w & 3;
    k = kc*16 + 2*q + (j&1) + (j&2)*4;
  }
  WBUF[idx] = __float2half_rn(src[k*N + n]);
}

// ---------------------------------------------------------------------------
// GEMM1 path: k16 chunks, B via LDG.64 (uint2), distance-1 double buffer.
// ---------------------------------------------------------------------------
template<int K, int N, int WM, int WN, int PA>
static __device__ __forceinline__ void run_g16(const __half* __restrict__ gB,
                  uint32_t As_u32, float* acc, int lane, int mi, int nj)
{
  constexpr int NK = K/16;
  const uint2* __restrict__ bp = reinterpret_cast<const uint2*>(gB)
      + (lane & 3) + ((nj*WN)*8 + (lane>>2))*4;
  const int g = lane >> 3, r = lane & 7;
  const uint32_t aaddr = As_u32
      + ((uint32_t)(((mi*WM)*16 + r + (g&1)*8)*PA + (g>>1)*8))*2u;

  uint2    b[2][WN];
  uint32_t a[2][WM][4];
  #pragma unroll
  for (int wn=0; wn<WN; wn++) b[0][wn] = __ldg(bp + wn*32);
  #pragma unroll
  for (int wm=0; wm<WM; wm++) ldsm4(a[0][wm], aaddr + wm*(16*PA*2));

  #pragma unroll 4
  for (int kc=0; kc<NK; kc++){
    const int cur = kc & 1, nxt = cur ^ 1;
    if (kc+1 < NK){
      #pragma unroll
      for (int wn=0; wn<WN; wn++) b[nxt][wn] = __ldg(bp + (kc+1)*(N*4) + wn*32);
      #pragma unroll
      for (int wm=0; wm<WM; wm++) ldsm4(a[nxt][wm], aaddr + wm*(16*PA*2) + (kc+1)*32);
    }
    #pragma unroll
    for (int wn=0; wn<WN; wn++){
      #pragma unroll
      for (int wm=0; wm<WM; wm++)
        mma16(acc+(wm*WN+wn)*4, a[cur][wm], b[cur][wn].x, b[cur][wn].y);
    }
  }
}

// ---------------------------------------------------------------------------
// k32 path: one LDG.128 per (wn, k32 chunk) = B for two m16n8k16 steps.
// A via ldmatrix parity-indexed (a[0]=even k16, a[1]=odd), distance-1.
// ---------------------------------------------------------------------------
template<int K, int N, int WM, int WN, int PA>
static __device__ __forceinline__ void run_g32(const __half* __restrict__ gB,
                  uint32_t As_u32, float* acc, int lane, int mi, int nj)
{
  constexpr int NK = K/32;
  const uint4* __restrict__ bp = reinterpret_cast<const uint4*>(gB)
      + (lane & 3) + ((nj*WN)*8 + (lane>>2))*4;
  const int g = lane >> 3, r = lane & 7;
  const uint32_t aaddr = As_u32
      + ((uint32_t)(((mi*WM)*16 + r + (g&1)*8)*PA + (g>>1)*8))*2u;

  uint4    b[2][WN];
  uint32_t a[2][WM][4];
  #pragma unroll
  for (int wn=0; wn<WN; wn++) b[0][wn] = __ldg(bp + wn*32);
  #pragma unroll
  for (int wm=0; wm<WM; wm++) ldsm4(a[0][wm], aaddr + wm*(16*PA*2));   // k16 idx 0

  #pragma unroll
  for (int kc=0; kc<NK; kc++){
    const int cur = kc & 1, nxt = cur ^ 1;
    if (kc+1 < NK){
      #pragma unroll
      for (int wn=0; wn<WN; wn++) b[nxt][wn] = __ldg(bp + (kc+1)*(N*4) + wn*32);
    }
    // A for odd sub-step (k16 idx 2kc+1)
    #pragma unroll
    for (int wm=0; wm<WM; wm++)
      ldsm4(a[1][wm], aaddr + wm*(16*PA*2) + (2*kc+1)*32);
    // sub-step 0: uses a[0], b .x/.y
    #pragma unroll
    for (int wn=0; wn<WN; wn++){
      #pragma unroll
      for (int wm=0; wm<WM; wm++)
        mma16(acc+(wm*WN+wn)*4, a[0][wm], b[cur][wn].x, b[cur][wn].y);
    }
    // A for next even sub-step (k16 idx 2kc+2)
    if (kc+1 < NK){
      #pragma unroll
      for (int wm=0; wm<WM; wm++)
        ldsm4(a[0][wm], aaddr + wm*(16*PA*2) + (2*kc+2)*32);
    }
    // sub-step 1: uses a[1], b .z/.w
    #pragma unroll
    for (int wn=0; wn<WN; wn++){
      #pragma unroll
      for (int wm=0; wm<WM; wm++)
        mma16(acc+(wm*WN+wn)*4, a[1][wm], b[cur][wn].z, b[cur][wn].w);
    }
  }
}

static __device__ __forceinline__ float sspf(float v, float cssp){
  float sp = fmaxf(v, 0.0f) + log1pf(expf(-fabsf(v)));
  return cssp * (sp - 0.69314718055994531f);
}

__global__ void __launch_bounds__(NT, 2)
resblk_kernel(const float* __restrict__ x, float* __restrict__ out, float cssp)
{
  extern __shared__ float sm[];
  float*  segf = sm;                         // float staging views
  __half* segh = reinterpret_cast<__half*>(sm);  // fp16 A/V tile views
  float*  G    = sm + G_OFF;
  uint32_t sm_u32;
  { uint32_t a; asm("{ .reg .u64 t; cvta.to.shared.u64 t, %1; cvt.u32.u64 %0, t; }"
                    : "=r"(a) : "l"(sm)); sm_u32 = a; }

  const int tid  = threadIdx.x;
  const int lane = tid & 31;
  const int warp = tid >> 5;            // 0..7
  const int nj2  = warp;                // scalar path: 1M x 8N
  const int mi4  = warp >> 2;           // vector paths: 2M x 4N
  const int nj4  = warp & 3;
  const int n0   = blockIdx.x * TILE;
  const float RS128 = 0.08838834764831845f;
  const float RS64  = 0.125f;

  // ================= scalar path =================
  // A0 = fp16(x0 tile)  [32 x 256], pitch PA0
  for (int t=tid; t<(TILE*256)/4; t+=NT){
    int e=t*4; int ln=e>>8; int col=e&255;
    float4 v = *reinterpret_cast<const float4*>(x + (size_t)(n0+ln)*960 + col);
    *reinterpret_cast<__half2*>(segh + ln*PA0 + col)     = __floats2half2_rn(v.x, v.y);
    *reinterpret_cast<__half2*>(segh + ln*PA0 + col + 2) = __floats2half2_rn(v.z, v.w);
  }
  __syncthreads();
  // s = A0 @ w1s / 16, SSP -> scalars(segh, fp16) + gates(G, fp32)
  {
    float acc[56];
    #pragma unroll
    for (int i=0;i<56;i++) acc[i]=0.f;
    run_g16<256,448,2,7,PA0>(&WBUF[W1S_OFF], sm_u32, acc, lane, 0, nj2);
    __syncthreads();
    #pragma unroll
    for (int wm=0; wm<2; wm++){
      #pragma unroll
      for (int wn=0; wn<7; wn++){
        #pragma unroll
        for (int q=0;q<4;q++){
          int row = wm*16 + (lane>>2) + ((q&2)<<2);
          int col = (nj2*7+wn)*8 + ((lane&3)<<1) + (q&1);
          float h = sspf(acc[(wm*7+wn)*4+q]*0.0625f, cssp);
          if (col < 256) segh[row*PA0 + col] = __float2half_rn(h);
          else           G[row*196 + (col-256)] = h;
        }
      }
    }
  }
  __syncthreads();
  // y0 = scalars @ w2s / 16 ; stage (fp32) then coalesced residual write
  {
    float acc[32];
    #pragma unroll
    for (int i=0;i<32;i++) acc[i]=0.f;
    run_g32<256,256,2,4,PA0>(&WBUF[W2S_OFF], sm_u32, acc, lane, 0, nj2);
    __syncthreads();
    #pragma unroll
    for (int wm=0; wm<2; wm++){
      #pragma unroll
      for (int wn=0; wn<4; wn++){
        #pragma unroll
        for (int q=0;q<4;q++){
          int row = wm*16 + (lane>>2) + ((q&2)<<2);
          int col = (nj2*4+wn)*8 + ((lane&3)<<1) + (q&1);
          segf[row*260 + col] = acc[(wm*4+wn)*4+q]*0.0625f;
        }
      }
    }
    __syncthreads();
    for (int t=tid; t<TILE*64; t+=NT){
      int ln=t>>6; int j=(t&63)*4;
      size_t off = (size_t)(n0+ln)*960 + j;
      float4 xr = *reinterpret_cast<const float4*>(x + off);
      float4 yv = *reinterpret_cast<const float4*>(segf + ln*260 + j);
      *reinterpret_cast<float4*>(out + off) =
        make_float4(xr.x+yv.x, xr.y+yv.y, xr.z+yv.z, xr.w+yv.w);
    }
  }
  __syncthreads();

  // ================= v1 path =================
  // A1[c*32+n][i] = fp16(x[n, 256+3i+c])  [96 x 128], pitch PA1
  for (int t=tid; t<(TILE*384)/4; t+=NT){
    int e=t*4; int ln=e/384; int j=e-ln*384;
    float4 v = *reinterpret_cast<const float4*>(x + (size_t)(n0+ln)*960 + 256 + j);
    float vv[4]={v.x,v.y,v.z,v.w};
    #pragma unroll
    for (int q=0;q<4;q++){
      int jj=j+q; int i3=jj/3; int c=jj-i3*3;
      segh[(c*32+ln)*PA1 + i3] = __float2half_rn(vv[q]);
    }
  }
  __syncthreads();
  // V1 = A1 @ w1v1 * rs128, gated, in place (fp16)
  {
    float acc[48];
    #pragma unroll
    for (int i=0;i<48;i++) acc[i]=0.f;
    run_g32<128,128,3,4,PA1>(&WBUF[W1V1_OFF], sm_u32, acc, lane, mi4, nj4);
    __syncthreads();
    #pragma unroll
    for (int wm=0; wm<3; wm++){
      #pragma unroll
      for (int wn=0; wn<4; wn++){
        #pragma unroll
        for (int q=0;q<4;q++){
          int row = (mi4*3+wm)*16 + (lane>>2) + ((q&2)<<2);
          int col = (nj4*4+wn)*8 + ((lane&3)<<1) + (q&1);
          float g = G[(row&31)*196 + col];
          segh[row*PA1 + col] = __float2half_rn(acc[(wm*4+wn)*4+q]*RS128*g);
        }
      }
    }
  }
  __syncthreads();
  // Y1 = V1 @ w2v1 * rs128 -> stage [n][3o+c] (fp32) -> coalesced residual write
  {
    float acc[48];
    #pragma unroll
    for (int i=0;i<48;i++) acc[i]=0.f;
    run_g32<128,128,3,4,PA1>(&WBUF[W2V1_OFF], sm_u32, acc, lane, mi4, nj4);
    __syncthreads();
    #pragma unroll
    for (int wm=0; wm<3; wm++){
      #pragma unroll
      for (int wn=0; wn<4; wn++){
        #pragma unroll
        for (int q=0;q<4;q++){
          int row = (mi4*3+wm)*16 + (lane>>2) + ((q&2)<<2);
          int col = (nj4*4+wn)*8 + ((lane&3)<<1) + (q&1);
          int n = row & 31; int c = row >> 5;
          segf[n*388 + 3*col + c] = acc[(wm*4+wn)*4+q]*RS128;
        }
      }
    }
    __syncthreads();
    for (int t=tid; t<TILE*96; t+=NT){
      int ln=t/96; int j=(t-ln*96)*4;
      size_t off = (size_t)(n0+ln)*960 + 256 + j;
      float4 xr = *reinterpret_cast<const float4*>(x + off);
      float4 yv = *reinterpret_cast<const float4*>(segf + ln*388 + j);
      *reinterpret_cast<float4*>(out + off) =
        make_float4(xr.x+yv.x, xr.y+yv.y, xr.z+yv.z, xr.w+yv.w);
    }
  }
  __syncthreads();

  // ================= v2 path =================
  // A2[c*32+n][i] = fp16(x[n, 640+5i+c])  [160 x 64], pitch PA2
  for (int t=tid; t<(TILE*320)/4; t+=NT){
    int e=t*4; int ln=e/320; int j=e-ln*320;
    float4 v = *reinterpret_cast<const float4*>(x + (size_t)(n0+ln)*960 + 640 + j);
    float vv[4]={v.x,v.y,v.z,v.w};
    #pragma unroll
    for (int q=0;q<4;q++){
      int jj=j+q; int i5=jj/5; int c=jj-i5*5;
      segh[(c*32+ln)*PA2 + i5] = __float2half_rn(vv[q]);
    }
  }
  __syncthreads();
  // V2 = A2 @ w1v2 * rs64, gated, in place (fp16)
  {
    float acc[40];
    #pragma unroll
    for (int i=0;i<40;i++) acc[i]=0.f;
    run_g32<64,64,5,2,PA2>(&WBUF[W1V2_OFF], sm_u32, acc, lane, mi4, nj4);
    __syncthreads();
    #pragma unroll
    for (int wm=0; wm<5; wm++){
      #pragma unroll
      for (int wn=0; wn<2; wn++){
        #pragma unroll
        for (int q=0;q<4;q++){
          int row = (mi4*5+wm)*16 + (lane>>2) + ((q&2)<<2);
          int col = (nj4*2+wn)*8 + ((lane&3)<<1) + (q&1);
          float g = G[(row&31)*196 + 128 + col];
          segh[row*PA2 + col] = __float2half_rn(acc[(wm*2+wn)*4+q]*RS64*g);
        }
      }
    }
  }
  __syncthreads();
  // Y2 = V2 @ w2v2 * rs64 -> stage [n][5o+c] (fp32) -> coalesced residual write
  {
    float acc[40];
    #pragma unroll
    for (int i=0;i<40;i++) acc[i]=0.f;
    run_g32<64,64,5,2,PA2>(&WBUF[W2V2_OFF], sm_u32, acc, lane, mi4, nj4);
    __syncthreads();
    #pragma unroll
    for (int wm=0; wm<5; wm++){
      #pragma unroll
      for (int wn=0; wn<2; wn++){
        #pragma unroll
        for (int q=0;q<4;q++){
          int row = (mi4*5+wm)*16 + (lane>>2) + ((q&2)<<2);
          int col = (nj4*2+wn)*8 + ((lane&3)<<1) + (q&1);
          int n = row & 31; int c = row >> 5;
          segf[n*324 + 5*col + c] = acc[(wm*2+wn)*4+q]*RS64;
        }
      }
    }
    __syncthreads();
    for (int t=tid; t<TILE*80; t+=NT){
      int ln=t/80; int j=(t-ln*80)*4;
      size_t off = (size_t)(n0+ln)*960 + 640 + j;
      float4 xr = *reinterpret_cast<const float4*>(x + off);
      float4 yv = *reinterpret_cast<const float4*>(segf + ln*324 + j);
      *reinterpret_cast<float4*>(out + off) =
        make_float4(xr.x+yv.x, xr.y+yv.y, xr.z+yv.z, xr.w+yv.w);
    }
  }
}

static double compute_cssp_host(){
  const int NP = 200001;
  const double LOG2 = 0.6931471805599453094172321214581766;
  double s = 0.0;
  for (int i=0;i<NP;i++){
    double z = -10.0 + (20.0 * i) / (NP - 1);
    double phi = exp(-0.5*z*z) / sqrt(2.0*3.14159265358979323846);
    double sp  = (z > 0.0) ? (z + log1p(exp(-z))) : log1p(exp(z));
    double f   = sp - LOG2;
    double w   = (i==0 || i==NP-1) ? 0.5 : 1.0;
    s += w * f * f * phi;
  }
  s *= 20.0 / (NP - 1);
  return 1.0 / sqrt(s);
}

extern "C" void kernel_launch(void* const* d_in, const int* in_sizes, int n_in,
                              void* d_out, int out_size) {
  const float* x    = (const float*)d_in[0];
  const float* w1s  = (const float*)d_in[1];
  const float* w1v1 = (const float*)d_in[2];
  const float* w1v2 = (const float*)d_in[3];
  const float* w2s  = (const float*)d_in[4];
  const float* w2v1 = (const float*)d_in[5];
  const float* w2v2 = (const float*)d_in[6];
  float* out = (float*)d_out;

  int n = in_sizes[0] / 960;

  static bool attr_done = false;
  if (!attr_done){
    cudaFuncSetAttribute(resblk_kernel,
        cudaFuncAttributeMaxDynamicSharedMemorySize, SMEM_FLOATS*4);
    attr_done = true;
  }
  static const float cssp = (float)compute_cssp_host();

  prep_weights<<<(WBUF_SZ + NT - 1)/NT, NT>>>(w1s, w1v1, w1v2, w2s, w2v1, w2v2);
  resblk_kernel<<<n/TILE, NT, SMEM_FLOATS*4>>>(x, out, cssp);
}

// round 12
// speedup vs baseline: 1.5953x; 1.1785x over previous
#include <cuda_runtime.h>
#include <cuda_fp16.h>
#include <cstdint>
#include <math.h>

#define NT 256
#define TILE 16
#define G_OFF    6208         // seg: y1 stage (16 x 388 floats) is the largest occupant
#define SMEM_FLOATS 9344      // + G (16 x 196 floats) = 37376 bytes per CTA (x3 = 112KB/SM)

// A-tile pitches in fp16 elements (row bytes = 16 * odd -> conflict-free ldmatrix)
#define PA0 264
#define PA1 136
#define PA2 72

// Pre-converted fp16 weights (filled by prep_weights).
// w1s: k16-chunk packing (uint2 per lane-fragment). Others: k32-chunk packing
// (uint4 per lane = B fragments for two consecutive m16n8k16 steps).
#define W1S_OFF   0
#define W2S_OFF   114688
#define W1V1_OFF  180224
#define W2V1_OFF  196608
#define W1V2_OFF  212992
#define W2V2_OFF  217088
#define WBUF_SZ   221184
__device__ __half WBUF[WBUF_SZ];

static __device__ __forceinline__ void mma16(float* d, const uint32_t* a,
                                             uint32_t b0, uint32_t b1){
  asm volatile("mma.sync.aligned.m16n8k16.row.col.f32.f16.f16.f32 "
      "{%0,%1,%2,%3}, {%4,%5,%6,%7}, {%8,%9}, {%0,%1,%2,%3};"
      : "+f"(d[0]), "+f"(d[1]), "+f"(d[2]), "+f"(d[3])
      : "r"(a[0]), "r"(a[1]), "r"(a[2]), "r"(a[3]), "r"(b0), "r"(b1));
}

// One ldmatrix.x4 = whole 16x16 fp16 A fragment (a0..a3) for one m16k16 tile.
static __device__ __forceinline__ void ldsm4(uint32_t* r, uint32_t addr){
  asm volatile("ldmatrix.sync.aligned.m8n8.x4.shared.b16 {%0,%1,%2,%3}, [%4];"
      : "=r"(r[0]), "=r"(r[1]), "=r"(r[2]), "=r"(r[3]) : "r"(addr));
}

// ---------------------------------------------------------------------------
// Init kernel: fp16-convert + permute weights (identical packing to R11).
// ---------------------------------------------------------------------------
__global__ void prep_weights(const float* __restrict__ w1s,
                             const float* __restrict__ w1v1,
                             const float* __restrict__ w1v2,
                             const float* __restrict__ w2s,
                             const float* __restrict__ w2v1,
                             const float* __restrict__ w2v2)
{
  int idx = blockIdx.x * blockDim.x + threadIdx.x;
  if (idx >= WBUF_SZ) return;
  const float* src; int N, loc; bool p32 = true;
  if      (idx < W2S_OFF)  { src = w1s;  N = 448; loc = idx - W1S_OFF; p32 = false; }
  else if (idx < W1V1_OFF) { src = w2s;  N = 256; loc = idx - W2S_OFF;  }
  else if (idx < W2V1_OFF) { src = w1v1; N = 128; loc = idx - W1V1_OFF; }
  else if (idx < W1V2_OFF) { src = w2v1; N = 128; loc = idx - W2V1_OFF; }
  else if (idx < W2V2_OFF) { src = w1v2; N = 64;  loc = idx - W1V2_OFF; }
  else                     { src = w2v2; N = 64;  loc = idx - W2V2_OFF; }
  int k, n;
  if (p32){
    int kc = loc / (N*32); int r = loc - kc*N*32; n = r >> 5; int w = r & 31;
    int q = w >> 3, t = w & 7;
    k = kc*32 + (t>>2)*16 + 2*q + (t&1) + (t&2)*4;
  } else {
    int kc = loc / (N*16); int r = loc - kc*N*16; n = r >> 4; int w = r & 15;
    int q = w >> 2, j = w & 3;
    k = kc*16 + 2*q + (j&1) + (j&2)*4;
  }
  WBUF[idx] = __float2half_rn(src[k*N + n]);
}

// ---------------------------------------------------------------------------
// GEMM1 path: k16 chunks, B via LDG.64 (uint2), distance-1 double buffer.
// ---------------------------------------------------------------------------
template<int K, int N, int WM, int WN, int PA>
static __device__ __forceinline__ void run_g16(const __half* __restrict__ gB,
                  uint32_t As_u32, float* acc, int lane, int mi, int nj)
{
  constexpr int NK = K/16;
  const uint2* __restrict__ bp = reinterpret_cast<const uint2*>(gB)
      + (lane & 3) + ((nj*WN)*8 + (lane>>2))*4;
  const int g = lane >> 3, r = lane & 7;
  const uint32_t aaddr = As_u32
      + ((uint32_t)(((mi*WM)*16 + r + (g&1)*8)*PA + (g>>1)*8))*2u;

  uint2    b[2][WN];
  uint32_t a[2][WM][4];
  #pragma unroll
  for (int wn=0; wn<WN; wn++) b[0][wn] = __ldg(bp + wn*32);
  #pragma unroll
  for (int wm=0; wm<WM; wm++) ldsm4(a[0][wm], aaddr + wm*(16*PA*2));

  #pragma unroll 4
  for (int kc=0; kc<NK; kc++){
    const int cur = kc & 1, nxt = cur ^ 1;
    if (kc+1 < NK){
      #pragma unroll
      for (int wn=0; wn<WN; wn++) b[nxt][wn] = __ldg(bp + (kc+1)*(N*4) + wn*32);
      #pragma unroll
      for (int wm=0; wm<WM; wm++) ldsm4(a[nxt][wm], aaddr + wm*(16*PA*2) + (kc+1)*32);
    }
    #pragma unroll
    for (int wn=0; wn<WN; wn++){
      #pragma unroll
      for (int wm=0; wm<WM; wm++)
        mma16(acc+(wm*WN+wn)*4, a[cur][wm], b[cur][wn].x, b[cur][wn].y);
    }
  }
}

// ---------------------------------------------------------------------------
// k32 path: one LDG.128 per (wn, k32 chunk) = B for two m16n8k16 steps.
// A via ldmatrix parity-indexed, distance-1.
// ---------------------------------------------------------------------------
template<int K, int N, int WM, int WN, int PA>
static __device__ __forceinline__ void run_g32(const __half* __restrict__ gB,
                  uint32_t As_u32, float* acc, int lane, int mi, int nj)
{
  constexpr int NK = K/32;
  const uint4* __restrict__ bp = reinterpret_cast<const uint4*>(gB)
      + (lane & 3) + ((nj*WN)*8 + (lane>>2))*4;
  const int g = lane >> 3, r = lane & 7;
  const uint32_t aaddr = As_u32
      + ((uint32_t)(((mi*WM)*16 + r + (g&1)*8)*PA + (g>>1)*8))*2u;

  uint4    b[2][WN];
  uint32_t a[2][WM][4];
  #pragma unroll
  for (int wn=0; wn<WN; wn++) b[0][wn] = __ldg(bp + wn*32);
  #pragma unroll
  for (int wm=0; wm<WM; wm++) ldsm4(a[0][wm], aaddr + wm*(16*PA*2));   // k16 idx 0

  #pragma unroll
  for (int kc=0; kc<NK; kc++){
    const int cur = kc & 1, nxt = cur ^ 1;
    if (kc+1 < NK){
      #pragma unroll
      for (int wn=0; wn<WN; wn++) b[nxt][wn] = __ldg(bp + (kc+1)*(N*4) + wn*32);
    }
    #pragma unroll
    for (int wm=0; wm<WM; wm++)
      ldsm4(a[1][wm], aaddr + wm*(16*PA*2) + (2*kc+1)*32);
    #pragma unroll
    for (int wn=0; wn<WN; wn++){
      #pragma unroll
      for (int wm=0; wm<WM; wm++)
        mma16(acc+(wm*WN+wn)*4, a[0][wm], b[cur][wn].x, b[cur][wn].y);
    }
    if (kc+1 < NK){
      #pragma unroll
      for (int wm=0; wm<WM; wm++)
        ldsm4(a[0][wm], aaddr + wm*(16*PA*2) + (2*kc+2)*32);
    }
    #pragma unroll
    for (int wn=0; wn<WN; wn++){
      #pragma unroll
      for (int wm=0; wm<WM; wm++)
        mma16(acc+(wm*WN+wn)*4, a[1][wm], b[cur][wn].z, b[cur][wn].w);
    }
  }
}

static __device__ __forceinline__ float sspf(float v, float cssp){
  float sp = fmaxf(v, 0.0f) + log1pf(expf(-fabsf(v)));
  return cssp * (sp - 0.69314718055994531f);
}

__global__ void __launch_bounds__(NT, 3)
resblk_kernel(const float* __restrict__ x, float* __restrict__ out, float cssp)
{
  extern __shared__ float sm[];
  float*  segf = sm;                             // float staging views
  __half* segh = reinterpret_cast<__half*>(sm);  // fp16 A/V tile views
  float*  G    = sm + G_OFF;
  uint32_t sm_u32;
  { uint32_t a; asm("{ .reg .u64 t; cvta.to.shared.u64 t, %1; cvt.u32.u64 %0, t; }"
                    : "=r"(a) : "l"(sm)); sm_u32 = a; }

  const int tid  = threadIdx.x;
  const int lane = tid & 31;
  const int warp = tid >> 5;            // 0..7 = N-group for every GEMM
  const int n0   = blockIdx.x * TILE;
  const float RS128 = 0.08838834764831845f;
  const float RS64  = 0.125f;

  // ================= scalar path =================
  // A0 = fp16(x0 tile)  [16 x 256], pitch PA0
  for (int t=tid; t<(TILE*256)/4; t+=NT){
    int e=t*4; int ln=e>>8; int col=e&255;
    float4 v = *reinterpret_cast<const float4*>(x + (size_t)(n0+ln)*960 + col);
    *reinterpret_cast<__half2*>(segh + ln*PA0 + col)     = __floats2half2_rn(v.x, v.y);
    *reinterpret_cast<__half2*>(segh + ln*PA0 + col + 2) = __floats2half2_rn(v.z, v.w);
  }
  __syncthreads();
  // s = A0 @ w1s / 16, SSP -> scalars(segh, fp16) + gates(G, fp32)
  {
    float acc[28];
    #pragma unroll
    for (int i=0;i<28;i++) acc[i]=0.f;
    run_g16<256,448,1,7,PA0>(&WBUF[W1S_OFF], sm_u32, acc, lane, 0, warp);
    __syncthreads();
    #pragma unroll
    for (int wn=0; wn<7; wn++){
      #pragma unroll
      for (int q=0;q<4;q++){
        int row = (lane>>2) + ((q&2)<<2);
        int col = (warp*7+wn)*8 + ((lane&3)<<1) + (q&1);
        float h = sspf(acc[wn*4+q]*0.0625f, cssp);
        if (col < 256) segh[row*PA0 + col] = __float2half_rn(h);
        else           G[row*196 + (col-256)] = h;
      }
    }
  }
  __syncthreads();
  // y0 = scalars @ w2s / 16 ; stage (fp32) then coalesced residual write
  {
    float acc[16];
    #pragma unroll
    for (int i=0;i<16;i++) acc[i]=0.f;
    run_g32<256,256,1,4,PA0>(&WBUF[W2S_OFF], sm_u32, acc, lane, 0, warp);
    __syncthreads();
    #pragma unroll
    for (int wn=0; wn<4; wn++){
      #pragma unroll
      for (int q=0;q<4;q++){
        int row = (lane>>2) + ((q&2)<<2);
        int col = (warp*4+wn)*8 + ((lane&3)<<1) + (q&1);
        segf[row*260 + col] = acc[wn*4+q]*0.0625f;
      }
    }
    __syncthreads();
    for (int t=tid; t<TILE*64; t+=NT){
      int ln=t>>6; int j=(t&63)*4;
      size_t off = (size_t)(n0+ln)*960 + j;
      float4 xr = *reinterpret_cast<const float4*>(x + off);
      float4 yv = *reinterpret_cast<const float4*>(segf + ln*260 + j);
      *reinterpret_cast<float4*>(out + off) =
        make_float4(xr.x+yv.x, xr.y+yv.y, xr.z+yv.z, xr.w+yv.w);
    }
  }
  __syncthreads();

  // ================= v1 path =================
  // A1[c*16+n][i] = fp16(x[n, 256+3i+c])  [48 x 128], pitch PA1
  for (int t=tid; t<(TILE*384)/4; t+=NT){
    int e=t*4; int ln=e/384; int j=e-ln*384;
    float4 v = *reinterpret_cast<const float4*>(x + (size_t)(n0+ln)*960 + 256 + j);
    float vv[4]={v.x,v.y,v.z,v.w};
    #pragma unroll
    for (int q=0;q<4;q++){
      int jj=j+q; int i3=jj/3; int c=jj-i3*3;
      segh[(c*16+ln)*PA1 + i3] = __float2half_rn(vv[q]);
    }
  }
  __syncthreads();
  // V1 = A1 @ w1v1 * rs128, gated, in place (fp16)
  {
    float acc[24];
    #pragma unroll
    for (int i=0;i<24;i++) acc[i]=0.f;
    run_g32<128,128,3,2,PA1>(&WBUF[W1V1_OFF], sm_u32, acc, lane, 0, warp);
    __syncthreads();
    #pragma unroll
    for (int wm=0; wm<3; wm++){
      #pragma unroll
      for (int wn=0; wn<2; wn++){
        #pragma unroll
        for (int q=0;q<4;q++){
          int row = wm*16 + (lane>>2) + ((q&2)<<2);
          int col = (warp*2+wn)*8 + ((lane&3)<<1) + (q&1);
          float g = G[(row&15)*196 + col];
          segh[row*PA1 + col] = __float2half_rn(acc[(wm*2+wn)*4+q]*RS128*g);
        }
      }
    }
  }
  __syncthreads();
  // Y1 = V1 @ w2v1 * rs128 -> stage [n][3o+c] (fp32) -> coalesced residual write
  {
    float acc[24];
    #pragma unroll
    for (int i=0;i<24;i++) acc[i]=0.f;
    run_g32<128,128,3,2,PA1>(&WBUF[W2V1_OFF], sm_u32, acc, lane, 0, warp);
    __syncthreads();
    #pragma unroll
    for (int wm=0; wm<3; wm++){
      #pragma unroll
      for (int wn=0; wn<2; wn++){
        #pragma unroll
        for (int q=0;q<4;q++){
          int row = wm*16 + (lane>>2) + ((q&2)<<2);
          int col = (warp*2+wn)*8 + ((lane&3)<<1) + (q&1);
          int n = row & 15; int c = row >> 4;
          segf[n*388 + 3*col + c] = acc[(wm*2+wn)*4+q]*RS128;
        }
      }
    }
    __syncthreads();
    for (int t=tid; t<TILE*96; t+=NT){
      int ln=t/96; int j=(t-ln*96)*4;
      size_t off = (size_t)(n0+ln)*960 + 256 + j;
      float4 xr = *reinterpret_cast<const float4*>(x + off);
      float4 yv = *reinterpret_cast<const float4*>(segf + ln*388 + j);
      *reinterpret_cast<float4*>(out + off) =
        make_float4(xr.x+yv.x, xr.y+yv.y, xr.z+yv.z, xr.w+yv.w);
    }
  }
  __syncthreads();

  // ================= v2 path =================
  // A2[c*16+n][i] = fp16(x[n, 640+5i+c])  [80 x 64], pitch PA2
  for (int t=tid; t<(TILE*320)/4; t+=NT){
    int e=t*4; int ln=e/320; int j=e-ln*320;
    float4 v = *reinterpret_cast<const float4*>(x + (size_t)(n0+ln)*960 + 640 + j);
    float vv[4]={v.x,v.y,v.z,v.w};
    #pragma unroll
    for (int q=0;q<4;q++){
      int jj=j+q; int i5=jj/5; int c=jj-i5*5;
      segh[(c*16+ln)*PA2 + i5] = __float2half_rn(vv[q]);
    }
  }
  __syncthreads();
  // V2 = A2 @ w1v2 * rs64, gated, in place (fp16)
  {
    float acc[20];
    #pragma unroll
    for (int i=0;i<20;i++) acc[i]=0.f;
    run_g32<64,64,5,1,PA2>(&WBUF[W1V2_OFF], sm_u32, acc, lane, 0, warp);
    __syncthreads();
    #pragma unroll
    for (int wm=0; wm<5; wm++){
      #pragma unroll
      for (int q=0;q<4;q++){
        int row = wm*16 + (lane>>2) + ((q&2)<<2);
        int col = warp*8 + ((lane&3)<<1) + (q&1);
        float g = G[(row&15)*196 + 128 + col];
        segh[row*PA2 + col] = __float2half_rn(acc[wm*4+q]*RS64*g);
      }
    }
  }
  __syncthreads();
  // Y2 = V2 @ w2v2 * rs64 -> stage [n][5o+c] (fp32) -> coalesced residual write
  {
    float acc[20];
    #pragma unroll
    for (int i=0;i<20;i++) acc[i]=0.f;
    run_g32<64,64,5,1,PA2>(&WBUF[W2V2_OFF], sm_u32, acc, lane, 0, warp);
    __syncthreads();
    #pragma unroll
    for (int wm=0; wm<5; wm++){
      #pragma unroll
      for (int q=0;q<4;q++){
        int row = wm*16 + (lane>>2) + ((q&2)<<2);
        int col = warp*8 + ((lane&3)<<1) + (q&1);
        int n = row & 15; int c = row >> 4;
        segf[n*324 + 5*col + c] = acc[wm*4+q]*RS64;
      }
    }
    __syncthreads();
    for (int t=tid; t<TILE*80; t+=NT){
      int ln=t/80; int j=(t-ln*80)*4;
      size_t off = (size_t)(n0+ln)*960 + 640 + j;
      float4 xr = *reinterpret_cast<const float4*>(x + off);
      float4 yv = *reinterpret_cast<const float4*>(segf + ln*324 + j);
      *reinterpret_cast<float4*>(out + off) =
        make_float4(xr.x+yv.x, xr.y+yv.y, xr.z+yv.z, xr.w+yv.w);
    }
  }
}

static double compute_cssp_host(){
  const int NP = 200001;
  const double LOG2 = 0.6931471805599453094172321214581766;
  double s = 0.0;
  for (int i=0;i<NP;i++){
    double z = -10.0 + (20.0 * i) / (NP - 1);
    double phi = exp(-0.5*z*z) / sqrt(2.0*3.14159265358979323846);
    double sp  = (z > 0.0) ? (z + log1p(exp(-z))) : log1p(exp(z));
    double f   = sp - LOG2;
    double w   = (i==0 || i==NP-1) ? 0.5 : 1.0;
    s += w * f * f * phi;
  }
  s *= 20.0 / (NP - 1);
  return 1.0 / sqrt(s);
}

extern "C" void kernel_launch(void* const* d_in, const int* in_sizes, int n_in,
                              void* d_out, int out_size) {
  const float* x    = (const float*)d_in[0];
  const float* w1s  = (const float*)d_in[1];
  const float* w1v1 = (const float*)d_in[2];
  const float* w1v2 = (const float*)d_in[3];
  const float* w2s  = (const float*)d_in[4];
  const float* w2v1 = (const float*)d_in[5];
  const float* w2v2 = (const float*)d_in[6];
  float* out = (float*)d_out;

  int n = in_sizes[0] / 960;

  static bool attr_done = false;
  if (!attr_done){
    cudaFuncSetAttribute(resblk_kernel,
        cudaFuncAttributeMaxDynamicSharedMemorySize, SMEM_FLOATS*4);
    attr_done = true;
  }
  static const float cssp = (float)compute_cssp_host();

  prep_weights<<<(WBUF_SZ + NT - 1)/NT, NT>>>(w1s, w1v1, w1v2, w2s, w2v1, w2v2);
  resblk_kernel<<<n/TILE, NT, SMEM_FLOATS*4>>>(x, out, cssp);
}

// round 13
// speedup vs baseline: 1.6433x; 1.0301x over previous
#include <cuda_runtime.h>
#include <cuda_fp16.h>
#include <cstdint>
#include <math.h>

#define NT 256
#define TILE 16
#define G_OFF    6208         // seg: y1 stage (16 x 388 floats) is the largest occupant
#define SMEM_FLOATS 9344      // + G (16 x 196 floats) = 37376 bytes per CTA (x3 = 112KB/SM)

// A-tile pitches in fp16 elements (row bytes = 16 * odd -> conflict-free ldmatrix)
#define PA0 264
#define PA1 136
#define PA2 72

// Pre-converted fp16 weights (filled by prep_weights). ALL matrices use
// k32-chunk packing: uint4 per lane = B fragments for two m16n8k16 steps.
#define W1S_OFF   0
#define W2S_OFF   114688
#define W1V1_OFF  180224
#define W2V1_OFF  196608
#define W1V2_OFF  212992
#define W2V2_OFF  217088
#define WBUF_SZ   221184
__device__ __half WBUF[WBUF_SZ];

static __device__ __forceinline__ void mma16(float* d, const uint32_t* a,
                                             uint32_t b0, uint32_t b1){
  asm volatile("mma.sync.aligned.m16n8k16.row.col.f32.f16.f16.f32 "
      "{%0,%1,%2,%3}, {%4,%5,%6,%7}, {%8,%9}, {%0,%1,%2,%3};"
      : "+f"(d[0]), "+f"(d[1]), "+f"(d[2]), "+f"(d[3])
      : "r"(a[0]), "r"(a[1]), "r"(a[2]), "r"(a[3]), "r"(b0), "r"(b1));
}

// One ldmatrix.x4 = whole 16x16 fp16 A fragment (a0..a3) for one m16k16 tile.
static __device__ __forceinline__ void ldsm4(uint32_t* r, uint32_t addr){
  asm volatile("ldmatrix.sync.aligned.m8n8.x4.shared.b16 {%0,%1,%2,%3}, [%4];"
      : "=r"(r[0]), "=r"(r[1]), "=r"(r[2]), "=r"(r[3]) : "r"(addr));
}

// ---------------------------------------------------------------------------
// Init kernel: fp16-convert + permute ALL weights into k32-chunk packing:
//   WBUF[off + kc*N*32 + n*32 + w], w = q*8+t ->
//   k = kc*32 + (t>>2)*16 + 2q + (t&1) + (t&2)*4
// so lane q's uint4 at [n*32 + q*8] = fragments for both k16 halves.
// ---------------------------------------------------------------------------
__global__ void prep_weights(const float* __restrict__ w1s,
                             const float* __restrict__ w1v1,
                             const float* __restrict__ w1v2,
                             const float* __restrict__ w2s,
                             const float* __restrict__ w2v1,
                             const float* __restrict__ w2v2)
{
  int idx = blockIdx.x * blockDim.x + threadIdx.x;
  if (idx >= WBUF_SZ) return;
  const float* src; int N, loc;
  if      (idx < W2S_OFF)  { src = w1s;  N = 448; loc = idx - W1S_OFF;  }
  else if (idx < W1V1_OFF) { src = w2s;  N = 256; loc = idx - W2S_OFF;  }
  else if (idx < W2V1_OFF) { src = w1v1; N = 128; loc = idx - W1V1_OFF; }
  else if (idx < W1V2_OFF) { src = w2v1; N = 128; loc = idx - W2V1_OFF; }
  else if (idx < W2V2_OFF) { src = w1v2; N = 64;  loc = idx - W1V2_OFF; }
  else                     { src = w2v2; N = 64;  loc = idx - W2V2_OFF; }
  int kc = loc / (N*32); int r = loc - kc*N*32; int n = r >> 5; int w = r & 31;
  int q = w >> 3, t = w & 7;
  int k = kc*32 + (t>>2)*16 + 2*q + (t&1) + (t&2)*4;
  WBUF[idx] = __float2half_rn(src[k*N + n]);
}

// ---------------------------------------------------------------------------
// k32 GEMM: one LDG.128 per (wn, k32 chunk) = B for two m16n8k16 steps.
// DB=true : B register double-buffered one chunk ahead (distance-1).
// DB=false: B burst-loaded at step start (single buffer) — saves registers;
//           viable at 3 CTAs/SM where sibling CTAs L1-hit the same lines.
// A via ldmatrix, parity-indexed, distance-1. No barriers inside.
// ---------------------------------------------------------------------------
template<int K, int N, int WM, int WN, int PA, bool DB>
static __device__ __forceinline__ void run_g32(const __half* __restrict__ gB,
                  uint32_t As_u32, float* acc, int lane, int mi, int nj)
{
  constexpr int NK = K/32;
  const uint4* __restrict__ bp = reinterpret_cast<const uint4*>(gB)
      + (lane & 3) + ((nj*WN)*8 + (lane>>2))*4;
  const int g = lane >> 3, r = lane & 7;
  const uint32_t aaddr = As_u32
      + ((uint32_t)(((mi*WM)*16 + r + (g&1)*8)*PA + (g>>1)*8))*2u;

  uint4    b[DB?2:1][WN];
  uint32_t a[2][WM][4];
  #pragma unroll
  for (int wn=0; wn<WN; wn++) b[0][wn] = __ldg(bp + wn*32);
  #pragma unroll
  for (int wm=0; wm<WM; wm++) ldsm4(a[0][wm], aaddr + wm*(16*PA*2));   // k16 idx 0

  #pragma unroll
  for (int kc=0; kc<NK; kc++){
    const int cur = DB ? (kc & 1) : 0;
    if (DB){
      if (kc+1 < NK){
        #pragma unroll
        for (int wn=0; wn<WN; wn++) b[cur^1][wn] = __ldg(bp + (kc+1)*(N*4) + wn*32);
      }
    } else if (kc > 0){
      #pragma unroll
      for (int wn=0; wn<WN; wn++) b[0][wn] = __ldg(bp + kc*(N*4) + wn*32);
    }
    // A for odd sub-step (k16 idx 2kc+1)
    #pragma unroll
    for (int wm=0; wm<WM; wm++)
      ldsm4(a[1][wm], aaddr + wm*(16*PA*2) + (2*kc+1)*32);
    // sub-step 0: uses a[0], b .x/.y
    #pragma unroll
    for (int wn=0; wn<WN; wn++){
      #pragma unroll
      for (int wm=0; wm<WM; wm++)
        mma16(acc+(wm*WN+wn)*4, a[0][wm], b[cur][wn].x, b[cur][wn].y);
    }
    // A for next even sub-step (k16 idx 2kc+2)
    if (kc+1 < NK){
      #pragma unroll
      for (int wm=0; wm<WM; wm++)
        ldsm4(a[0][wm], aaddr + wm*(16*PA*2) + (2*kc+2)*32);
    }
    // sub-step 1: uses a[1], b .z/.w
    #pragma unroll
    for (int wn=0; wn<WN; wn++){
      #pragma unroll
      for (int wm=0; wm<WM; wm++)
        mma16(acc+(wm*WN+wn)*4, a[1][wm], b[cur][wn].z, b[cur][wn].w);
    }
  }
}

static __device__ __forceinline__ float sspf(float v, float cssp){
  float sp = fmaxf(v, 0.0f) + log1pf(expf(-fabsf(v)));
  return cssp * (sp - 0.69314718055994531f);
}

__global__ void __launch_bounds__(NT, 3)
resblk_kernel(const float* __restrict__ x, float* __restrict__ out, float cssp)
{
  extern __shared__ float sm[];
  float*  segf = sm;                             // float staging views
  __half* segh = reinterpret_cast<__half*>(sm);  // fp16 A/V tile views
  float*  G    = sm + G_OFF;
  uint32_t sm_u32;
  { uint32_t a; asm("{ .reg .u64 t; cvta.to.shared.u64 t, %1; cvt.u32.u64 %0, t; }"
                    : "=r"(a) : "l"(sm)); sm_u32 = a; }

  const int tid  = threadIdx.x;
  const int lane = tid & 31;
  const int warp = tid >> 5;            // 0..7 = N-group for every GEMM
  const int n0   = blockIdx.x * TILE;
  const float RS128 = 0.08838834764831845f;
  const float RS64  = 0.125f;

  // ================= scalar path =================
  // A0 = fp16(x0 tile)  [16 x 256], pitch PA0
  for (int t=tid; t<(TILE*256)/4; t+=NT){
    int e=t*4; int ln=e>>8; int col=e&255;
    float4 v = *reinterpret_cast<const float4*>(x + (size_t)(n0+ln)*960 + col);
    *reinterpret_cast<__half2*>(segh + ln*PA0 + col)     = __floats2half2_rn(v.x, v.y);
    *reinterpret_cast<__half2*>(segh + ln*PA0 + col + 2) = __floats2half2_rn(v.z, v.w);
  }
  __syncthreads();
  // s = A0 @ w1s / 16, SSP -> scalars(segh, fp16) + gates(G, fp32)
  {
    float acc[28];
    #pragma unroll
    for (int i=0;i<28;i++) acc[i]=0.f;
    run_g32<256,448,1,7,PA0,false>(&WBUF[W1S_OFF], sm_u32, acc, lane, 0, warp);
    __syncthreads();
    #pragma unroll
    for (int wn=0; wn<7; wn++){
      #pragma unroll
      for (int q=0;q<4;q++){
        int row = (lane>>2) + ((q&2)<<2);
        int col = (warp*7+wn)*8 + ((lane&3)<<1) + (q&1);
        float h = sspf(acc[wn*4+q]*0.0625f, cssp);
        if (col < 256) segh[row*PA0 + col] = __float2half_rn(h);
        else           G[row*196 + (col-256)] = h;
      }
    }
  }
  __syncthreads();
  // y0 = scalars @ w2s / 16 ; stage (fp32) then coalesced residual write
  {
    float acc[16];
    #pragma unroll
    for (int i=0;i<16;i++) acc[i]=0.f;
    run_g32<256,256,1,4,PA0,true>(&WBUF[W2S_OFF], sm_u32, acc, lane, 0, warp);
    __syncthreads();
    #pragma unroll
    for (int wn=0; wn<4; wn++){
      #pragma unroll
      for (int q=0;q<4;q++){
        int row = (lane>>2) + ((q&2)<<2);
        int col = (warp*4+wn)*8 + ((lane&3)<<1) + (q&1);
        segf[row*260 + col] = acc[wn*4+q]*0.0625f;
      }
    }
    __syncthreads();
    for (int t=tid; t<TILE*64; t+=NT){
      int ln=t>>6; int j=(t&63)*4;
      size_t off = (size_t)(n0+ln)*960 + j;
      float4 xr = *reinterpret_cast<const float4*>(x + off);
      float4 yv = *reinterpret_cast<const float4*>(segf + ln*260 + j);
      *reinterpret_cast<float4*>(out + off) =
        make_float4(xr.x+yv.x, xr.y+yv.y, xr.z+yv.z, xr.w+yv.w);
    }
  }
  __syncthreads();

  // ================= v1 path =================
  // A1[c*16+n][i] = fp16(x[n, 256+3i+c])  [48 x 128], pitch PA1
  for (int t=tid; t<(TILE*384)/4; t+=NT){
    int e=t*4; int ln=e/384; int j=e-ln*384;
    float4 v = *reinterpret_cast<const float4*>(x + (size_t)(n0+ln)*960 + 256 + j);
    float vv[4]={v.x,v.y,v.z,v.w};
    #pragma unroll
    for (int q=0;q<4;q++){
      int jj=j+q; int i3=jj/3; int c=jj-i3*3;
      segh[(c*16+ln)*PA1 + i3] = __float2half_rn(vv[q]);
    }
  }
  __syncthreads();
  // V1 = A1 @ w1v1 * rs128, gated, in place (fp16)
  {
    float acc[24];
    #pragma unroll
    for (int i=0;i<24;i++) acc[i]=0.f;
    run_g32<128,128,3,2,PA1,true>(&WBUF[W1V1_OFF], sm_u32, acc, lane, 0, warp);
    __syncthreads();
    #pragma unroll
    for (int wm=0; wm<3; wm++){
      #pragma unroll
      for (int wn=0; wn<2; wn++){
        #pragma unroll
        for (int q=0;q<4;q++){
          int row = wm*16 + (lane>>2) + ((q&2)<<2);
          int col = (warp*2+wn)*8 + ((lane&3)<<1) + (q&1);
          float g = G[(row&15)*196 + col];
          segh[row*PA1 + col] = __float2half_rn(acc[(wm*2+wn)*4+q]*RS128*g);
        }
      }
    }
  }
  __syncthreads();
  // Y1 = V1 @ w2v1 * rs128 -> stage [n][3o+c] (fp32) -> coalesced residual write
  {
    float acc[24];
    #pragma unroll
    for (int i=0;i<24;i++) acc[i]=0.f;
    run_g32<128,128,3,2,PA1,true>(&WBUF[W2V1_OFF], sm_u32, acc, lane, 0, warp);
    __syncthreads();
    #pragma unroll
    for (int wm=0; wm<3; wm++){
      #pragma unroll
      for (int wn=0; wn<2; wn++){
        #pragma unroll
        for (int q=0;q<4;q++){
          int row = wm*16 + (lane>>2) + ((q&2)<<2);
          int col = (warp*2+wn)*8 + ((lane&3)<<1) + (q&1);
          int n = row & 15; int c = row >> 4;
          segf[n*388 + 3*col + c] = acc[(wm*2+wn)*4+q]*RS128;
        }
      }
    }
    __syncthreads();
    for (int t=tid; t<TILE*96; t+=NT){
      int ln=t/96; int j=(t-ln*96)*4;
      size_t off = (size_t)(n0+ln)*960 + 256 + j;
      float4 xr = *reinterpret_cast<const float4*>(x + off);
      float4 yv = *reinterpret_cast<const float4*>(segf + ln*388 + j);
      *reinterpret_cast<float4*>(out + off) =
        make_float4(xr.x+yv.x, xr.y+yv.y, xr.z+yv.z, xr.w+yv.w);
    }
  }
  __syncthreads();

  // ================= v2 path =================
  // A2[c*16+n][i] = fp16(x[n, 640+5i+c])  [80 x 64], pitch PA2
  for (int t=tid; t<(TILE*320)/4; t+=NT){
    int e=t*4; int ln=e/320; int j=e-ln*320;
    float4 v = *reinterpret_cast<const float4*>(x + (size_t)(n0+ln)*960 + 640 + j);
    float vv[4]={v.x,v.y,v.z,v.w};
    #pragma unroll
    for (int q=0;q<4;q++){
      int jj=j+q; int i5=jj/5; int c=jj-i5*5;
      segh[(c*16+ln)*PA2 + i5] = __float2half_rn(vv[q]);
    }
  }
  __syncthreads();
  // V2 = A2 @ w1v2 * rs64, gated, in place (fp16)
  {
    float acc[20];
    #pragma unroll
    for (int i=0;i<20;i++) acc[i]=0.f;
    run_g32<64,64,5,1,PA2,true>(&WBUF[W1V2_OFF], sm_u32, acc, lane, 0, warp);
    __syncthreads();
    #pragma unroll
    for (int wm=0; wm<5; wm++){
      #pragma unroll
      for (int q=0;q<4;q++){
        int row = wm*16 + (lane>>2) + ((q&2)<<2);
        int col = warp*8 + ((lane&3)<<1) + (q&1);
        float g = G[(row&15)*196 + 128 + col];
        segh[row*PA2 + col] = __float2half_rn(acc[wm*4+q]*RS64*g);
      }
    }
  }
  __syncthreads();
  // Y2 = V2 @ w2v2 * rs64 -> stage [n][5o+c] (fp32) -> coalesced residual write
  {
    float acc[20];
    #pragma unroll
    for (int i=0;i<20;i++) acc[i]=0.f;
    run_g32<64,64,5,1,PA2,true>(&WBUF[W2V2_OFF], sm_u32, acc, lane, 0, warp);
    __syncthreads();
    #pragma unroll
    for (int wm=0; wm<5; wm++){
      #pragma unroll
      for (int q=0;q<4;q++){
        int row = wm*16 + (lane>>2) + ((q&2)<<2);
        int col = warp*8 + ((lane&3)<<1) + (q&1);
        int n = row & 15; int c = row >> 4;
        segf[n*324 + 5*col + c] = acc[wm*4+q]*RS64;
      }
    }
    __syncthreads();
    for (int t=tid; t<TILE*80; t+=NT){
      int ln=t/80; int j=(t-ln*80)*4;
      size_t off = (size_t)(n0+ln)*960 + 640 + j;
      float4 xr = *reinterpret_cast<const float4*>(x + off);
      float4 yv = *reinterpret_cast<const float4*>(segf + ln*324 + j);
      *reinterpret_cast<float4*>(out + off) =
        make_float4(xr.x+yv.x, xr.y+yv.y, xr.z+yv.z, xr.w+yv.w);
    }
  }
}

static double compute_cssp_host(){
  const int NP = 200001;
  const double LOG2 = 0.6931471805599453094172321214581766;
  double s = 0.0;
  for (int i=0;i<NP;i++){
    double z = -10.0 + (20.0 * i) / (NP - 1);
    double phi = exp(-0.5*z*z) / sqrt(2.0*3.14159265358979323846);
    double sp  = (z > 0.0) ? (z + log1p(exp(-z))) : log1p(exp(z));
    double f   = sp - LOG2;
    double w   = (i==0 || i==NP-1) ? 0.5 : 1.0;
    s += w * f * f * phi;
  }
  s *= 20.0 / (NP - 1);
  return 1.0 / sqrt(s);
}

extern "C" void kernel_launch(void* const* d_in, const int* in_sizes, int n_in,
                              void* d_out, int out_size) {
  const float* x    = (const float*)d_in[0];
  const float* w1s  = (const float*)d_in[1];
  const float* w1v1 = (const float*)d_in[2];
  const float* w1v2 = (const float*)d_in[3];
  const float* w2s  = (const float*)d_in[4];
  const float* w2v1 = (const float*)d_in[5];
  const float* w2v2 = (const float*)d_in[6];
  float* out = (float*)d_out;

  int n = in_sizes[0] / 960;

  static bool attr_done = false;
  if (!attr_done){
    cudaFuncSetAttribute(resblk_kernel,
        cudaFuncAttributeMaxDynamicSharedMemorySize, SMEM_FLOATS*4);
    attr_done = true;
  }
  static const float cssp = (float)compute_cssp_host();

  prep_weights<<<(WBUF_SZ + NT - 1)/NT, NT>>>(w1s, w1v1, w1v2, w2s, w2v1, w2v2);
  resblk_kernel<<<n/TILE, NT, SMEM_FLOATS*4>>>(x, out, cssp);
}